// round 7
// baseline (speedup 1.0000x reference)
#include <cuda_runtime.h>
#include <math.h>

#define NN 50000
#define EE 800000
#define NSPEC 10

// ---- scratch (static device globals; allocation-free) ----
__device__ float g_S[NN * 64];          // up-projected scalars [N,64]
__device__ float g_V[NN * 192];         // up-projected vectors [N,64,3]
__device__ float g_A[NN * 256];         // packed aggregation [N][64][4] = (s,vx,vy,vz)
__device__ int   g_cnt[16];             // per-species node counts
__device__ int   g_bkt[NSPEC * NN];     // per-species node lists
__device__ int   g_deg[NN];             // receiver histogram -> running offsets
__device__ int   g_eid[EE];             // receiver-sorted edge ids

__device__ __forceinline__ unsigned f2tf32(float x) {
    unsigned r;
    asm("cvt.rna.tf32.f32 %0, %1;" : "=r"(r) : "f"(x));
    return r;
}

// ============================================================================
// Species bucketing (warp-aggregated)
// ============================================================================
__global__ void k_zero_cnt() { if (threadIdx.x < 16) g_cnt[threadIdx.x] = 0; }

__global__ __launch_bounds__(256) void k_bucket(const int* __restrict__ specie, int N)
{
    int i = blockIdx.x * blockDim.x + threadIdx.x;
    if (i < N) {
        int sp = specie[i];
        unsigned mask = __match_any_sync(__activemask(), sp);
        int lane = threadIdx.x & 31;
        int leader = __ffs(mask) - 1;
        int rank = __popc(mask & ((1u << lane) - 1));
        int base = 0;
        if (lane == leader) base = atomicAdd(&g_cnt[sp], __popc(mask));
        base = __shfl_sync(mask, base, leader);
        g_bkt[sp * NN + base + rank] = i;
    }
}

// ============================================================================
// Receiver counting sort: zero -> histogram -> scan -> scatter
// ============================================================================
__global__ __launch_bounds__(256) void k_zero_deg(int N)
{
    int i = blockIdx.x * blockDim.x + threadIdx.x;
    if (i < N) g_deg[i] = 0;
}

__global__ __launch_bounds__(256) void k_hist(const int* __restrict__ receivers, int E)
{
    int i = blockIdx.x * blockDim.x + threadIdx.x;
    if (i < E) atomicAdd(&g_deg[receivers[i]], 1);
}

__global__ __launch_bounds__(1024) void k_scan(int N)
{
    __shared__ int part[1024];
    int t = threadIdx.x;
    int chunk = (N + 1023) >> 10;
    int s0 = t * chunk, s1 = s0 + chunk; if (s1 > N) s1 = N;
    int sum = 0;
    for (int i = s0; i < s1; i++) sum += g_deg[i];
    part[t] = sum;
    __syncthreads();
    for (int off = 1; off < 1024; off <<= 1) {
        int v = (t >= off) ? part[t - off] : 0;
        __syncthreads();
        part[t] += v;
        __syncthreads();
    }
    int run = (t == 0) ? 0 : part[t - 1];
    for (int i = s0; i < s1; i++) {
        int c = g_deg[i];
        g_deg[i] = run;
        run += c;
    }
}

__global__ __launch_bounds__(256) void k_scatter(const int* __restrict__ receivers, int E)
{
    int i = blockIdx.x * blockDim.x + threadIdx.x;
    if (i < E) {
        int pos = atomicAdd(&g_deg[receivers[i]], 1);
        g_eid[pos] = i;
    }
}

// ============================================================================
// Kernel A: linear-up + zero packed aggregation buffer.
// ============================================================================
__global__ __launch_bounds__(256) void k_up(
    const float* __restrict__ nfs, const float* __restrict__ nfv,
    const float* __restrict__ Wus, const float* __restrict__ Wuv, int N)
{
    extern __shared__ float su[];
    float4* wsv4 = (float4*)su;
    float*  s_in = su + 8192;
    float4* v_in = (float4*)(su + 8192 + 2048);

    int tid = threadIdx.x;
    const float2* us2 = (const float2*)Wus;
    const float2* uv2 = (const float2*)Wuv;
    for (int i = tid; i < 2048; i += 256) {
        float2 a = us2[i], b = uv2[i];
        wsv4[i] = make_float4(a.x, b.x, a.y, b.y);
    }
    __syncthreads();

    int warp = tid >> 5, lane = tid & 31;
    float*  ss = s_in + warp * 256;
    float4* vv = v_in + warp * 256;

    for (int base = blockIdx.x * 32 + warp * 4; base < N; base += gridDim.x * 32) {
        int nv = N - base; if (nv > 4) nv = 4;
        #pragma unroll
        for (int j = 0; j < 4; j++) {
            if (j < nv) {
                int n = base + j;
                float2 sv = *(const float2*)(nfs + (size_t)n * 64 + 2 * lane);
                ss[j * 64 + 2 * lane]     = sv.x;
                ss[j * 64 + 2 * lane + 1] = sv.y;
                const float2* vp = (const float2*)(nfv + (size_t)n * 192);
                float2 p0 = vp[lane * 3], p1 = vp[lane * 3 + 1], p2 = vp[lane * 3 + 2];
                vv[j * 64 + 2 * lane]     = make_float4(p0.x, p0.y, p1.x, 0.f);
                vv[j * 64 + 2 * lane + 1] = make_float4(p1.y, p2.x, p2.y, 0.f);
            }
        }
        __syncwarp();

        float acc[4][8];
        #pragma unroll
        for (int j = 0; j < 4; j++)
            #pragma unroll
            for (int q = 0; q < 8; q++) acc[j][q] = 0.f;

        #pragma unroll 4
        for (int f = 0; f < 64; f++) {
            float4 wq = wsv4[f * 32 + lane];
            #pragma unroll
            for (int j = 0; j < 4; j++) {
                float  sb = ss[j * 64 + f];
                float4 vb = vv[j * 64 + f];
                acc[j][0] = fmaf(sb, wq.x, acc[j][0]);
                acc[j][1] = fmaf(sb, wq.z, acc[j][1]);
                acc[j][2] = fmaf(vb.x, wq.y, acc[j][2]);
                acc[j][3] = fmaf(vb.y, wq.y, acc[j][3]);
                acc[j][4] = fmaf(vb.z, wq.y, acc[j][4]);
                acc[j][5] = fmaf(vb.x, wq.w, acc[j][5]);
                acc[j][6] = fmaf(vb.y, wq.w, acc[j][6]);
                acc[j][7] = fmaf(vb.z, wq.w, acc[j][7]);
            }
        }

        for (int j = 0; j < nv; j++) {
            int n = base + j;
            *(float2*)(g_S + (size_t)n * 64 + 2 * lane) = make_float2(acc[j][0], acc[j][1]);
            float2* vp = (float2*)(g_V + (size_t)n * 192);
            vp[lane * 3]     = make_float2(acc[j][2], acc[j][3]);
            vp[lane * 3 + 1] = make_float2(acc[j][4], acc[j][5]);
            vp[lane * 3 + 2] = make_float2(acc[j][6], acc[j][7]);
            float4* za = (float4*)(g_A + (size_t)n * 256);
            za[lane]      = make_float4(0.f, 0.f, 0.f, 0.f);
            za[32 + lane] = make_float4(0.f, 0.f, 0.f, 0.f);
        }
        __syncwarp();
    }
}

// ============================================================================
// Kernel B (FUSED, receiver-sorted): radial MLP on tensor cores -> C in SMEM
// -> messages with in-warp same-receiver combining -> vector-atomic scatter.
// Edges processed in g_eid (receiver-sorted) order.
// ============================================================================
__global__ __launch_bounds__(256) void k_edge(
    const float* __restrict__ RE, const float* __restrict__ Wr1,
    const float* __restrict__ Wr2, const float* __restrict__ vectors,
    const int* __restrict__ senders, const int* __restrict__ receivers, int En)
{
    extern __shared__ float sg[];
    unsigned* wr2u = (unsigned*)sg;                 // 64*328
    float*    csm  = sg + 20992;                    // 64*328
    unsigned* hu   = (unsigned*)(sg + 41984);       // 64*68
    float*    res  = sg + 41984 + 4352;             // 512
    float*    wr1s = res + 512;                     // 512

    int tid = threadIdx.x;
    for (int i = tid; i < 20480; i += 256) {
        int j = i / 320, n = i - j * 320;
        wr2u[j * 328 + n] = f2tf32(Wr2[i]);
    }
    for (int i = tid; i < 512; i += 256) wr1s[i] = Wr1[i];
    __syncthreads();

    int lane = tid & 31, warp = tid >> 5;
    int gid = lane >> 2, tig = lane & 3;
    int ntiles = (En + 63) >> 6;

    for (int t = blockIdx.x; t < ntiles; t += gridDim.x) {
        int e0 = t << 6;
        // stage RE tile (gather by sorted edge id)
        for (int i = tid; i < 512; i += 256) {
            int el = i >> 3;
            int e = e0 + el;
            float v = 0.f;
            if (e < En) {
                int eid = __ldg(g_eid + e);
                v = __ldg(RE + (size_t)eid * 8 + (i & 7));
            }
            res[i] = v;
        }
        __syncthreads();
        // h = silu(res @ W_r1) as tf32
        #pragma unroll
        for (int i = 0; i < 16; i++) {
            int idx = tid + 256 * i;
            int e = idx >> 6, j = idx & 63;
            const float* rr = res + e * 8;
            float a = 0.f;
            #pragma unroll
            for (int k = 0; k < 8; k++) a = fmaf(rr[k], wr1s[k * 64 + j], a);
            float hval = __fdividef(a, 1.f + __expf(-a));
            hu[e * 68 + j] = f2tf32(hval);
        }
        __syncthreads();

        // MMA: C[64,320] = h @ W_r2, warp owns 40-col strip
        float c[4][5][4];
        #pragma unroll
        for (int mt = 0; mt < 4; mt++)
            #pragma unroll
            for (int nt = 0; nt < 5; nt++)
                #pragma unroll
                for (int q = 0; q < 4; q++) c[mt][nt][q] = 0.f;

        #pragma unroll
        for (int ks = 0; ks < 8; ks++) {
            int kb = ks * 8;
            unsigned a[4][4];
            #pragma unroll
            for (int mt = 0; mt < 4; mt++) {
                int r0 = mt * 16 + gid;
                a[mt][0] = hu[r0 * 68 + kb + tig];
                a[mt][1] = hu[(r0 + 8) * 68 + kb + tig];
                a[mt][2] = hu[r0 * 68 + kb + tig + 4];
                a[mt][3] = hu[(r0 + 8) * 68 + kb + tig + 4];
            }
            #pragma unroll
            for (int nt = 0; nt < 5; nt++) {
                int col = warp * 40 + nt * 8 + gid;
                unsigned b0 = wr2u[(kb + tig) * 328 + col];
                unsigned b1 = wr2u[(kb + tig + 4) * 328 + col];
                #pragma unroll
                for (int mt = 0; mt < 4; mt++) {
                    asm volatile(
                        "mma.sync.aligned.m16n8k8.row.col.f32.tf32.tf32.f32 "
                        "{%0,%1,%2,%3}, {%4,%5,%6,%7}, {%8,%9}, {%0,%1,%2,%3};\n"
                        : "+f"(c[mt][nt][0]), "+f"(c[mt][nt][1]),
                          "+f"(c[mt][nt][2]), "+f"(c[mt][nt][3])
                        : "r"(a[mt][0]), "r"(a[mt][1]), "r"(a[mt][2]), "r"(a[mt][3]),
                          "r"(b0), "r"(b1));
                }
            }
        }
        // store C fragments into smem
        #pragma unroll
        for (int mt = 0; mt < 4; mt++) {
            int r0 = mt * 16 + gid;
            #pragma unroll
            for (int nt = 0; nt < 5; nt++) {
                int col = warp * 40 + nt * 8 + 2 * tig;
                *(float2*)(csm + r0 * 328 + col) = make_float2(c[mt][nt][0], c[mt][nt][1]);
                *(float2*)(csm + (r0 + 8) * 328 + col) = make_float2(c[mt][nt][2], c[mt][nt][3]);
            }
        }
        __syncthreads();

        // ---- messages: warp owns 8 consecutive sorted edges; combine runs of
        //      equal receiver in registers, flush with 2x red.v4 per run ----
        {
            int curR = -1;
            float A0 = 0.f, A1 = 0.f, A2 = 0.f, A3 = 0.f;
            float B0 = 0.f, B1 = 0.f, B2 = 0.f, B3 = 0.f;

            #pragma unroll
            for (int i = 0; i < 8; i++) {
                int el = warp * 8 + i;
                int e = e0 + el;
                if (e < En) {
                    int eid = __ldg(g_eid + e);
                    const float* cw = csm + el * 328;
                    float2 w0 = *(const float2*)(cw + 2 * lane);
                    float2 w1 = *(const float2*)(cw + 64 + 2 * lane);
                    float2 w2 = *(const float2*)(cw + 128 + 2 * lane);
                    float2 w3 = *(const float2*)(cw + 192 + 2 * lane);
                    float2 w4 = *(const float2*)(cw + 256 + 2 * lane);

                    int s = __ldg(senders + eid);
                    int r = __ldg(receivers + eid);
                    float vx = __ldg(vectors + (size_t)eid * 3 + 0);
                    float vy = __ldg(vectors + (size_t)eid * 3 + 1);
                    float vz = __ldg(vectors + (size_t)eid * 3 + 2);
                    float nrm = sqrtf(vx * vx + vy * vy + vz * vz);
                    float ri = 1.f / (nrm + 1e-9f);
                    float Y0 = vx * ri, Y1 = vy * ri, Y2 = vz * ri;

                    float2 xs = __ldg((const float2*)(g_S + (size_t)s * 64) + lane);
                    const float2* Vp = (const float2*)(g_V + (size_t)s * 192);
                    float2 p0 = __ldg(Vp + lane * 3 + 0);
                    float2 p1 = __ldg(Vp + lane * 3 + 1);
                    float2 p2 = __ldg(Vp + lane * 3 + 2);
                    float a0 = p0.x, a1 = p0.y, a2 = p1.x;
                    float b0 = p1.y, b1 = p2.x, b2 = p2.y;

                    float dota = a0 * Y0 + a1 * Y1 + a2 * Y2;
                    float dotb = b0 * Y0 + b1 * Y1 + b2 * Y2;

                    float msa = w0.x * xs.x + w3.x * dota;
                    float msb = w0.y * xs.y + w3.y * dotb;

                    float cxa0 = a1 * Y2 - a2 * Y1;
                    float cxa1 = a2 * Y0 - a0 * Y2;
                    float cxa2 = a0 * Y1 - a1 * Y0;
                    float cxb0 = b1 * Y2 - b2 * Y1;
                    float cxb1 = b2 * Y0 - b0 * Y2;
                    float cxb2 = b0 * Y1 - b1 * Y0;

                    float sa = w1.x * xs.x, sb = w1.y * xs.y;
                    float mva0 = sa * Y0 + w2.x * a0 + w4.x * cxa0;
                    float mva1 = sa * Y1 + w2.x * a1 + w4.x * cxa1;
                    float mva2 = sa * Y2 + w2.x * a2 + w4.x * cxa2;
                    float mvb0 = sb * Y0 + w2.y * b0 + w4.y * cxb0;
                    float mvb1 = sb * Y1 + w2.y * b1 + w4.y * cxb1;
                    float mvb2 = sb * Y2 + w2.y * b2 + w4.y * cxb2;

                    if (r != curR) {            // warp-uniform branch
                        if (curR >= 0) {
                            float* base = g_A + (size_t)curR * 256 + lane * 8;
                            asm volatile("red.global.add.v4.f32 [%0], {%1,%2,%3,%4};"
                                         :: "l"(base), "f"(A0), "f"(A1), "f"(A2), "f"(A3)
                                         : "memory");
                            asm volatile("red.global.add.v4.f32 [%0], {%1,%2,%3,%4};"
                                         :: "l"(base + 4), "f"(B0), "f"(B1), "f"(B2), "f"(B3)
                                         : "memory");
                        }
                        curR = r;
                        A0 = msa;  A1 = mva0; A2 = mva1; A3 = mva2;
                        B0 = msb;  B1 = mvb0; B2 = mvb1; B3 = mvb2;
                    } else {
                        A0 += msa;  A1 += mva0; A2 += mva1; A3 += mva2;
                        B0 += msb;  B1 += mvb0; B2 += mvb1; B3 += mvb2;
                    }
                }
            }
            if (curR >= 0) {
                float* base = g_A + (size_t)curR * 256 + lane * 8;
                asm volatile("red.global.add.v4.f32 [%0], {%1,%2,%3,%4};"
                             :: "l"(base), "f"(A0), "f"(A1), "f"(A2), "f"(A3)
                             : "memory");
                asm volatile("red.global.add.v4.f32 [%0], {%1,%2,%3,%4};"
                             :: "l"(base + 4), "f"(B0), "f"(B1), "f"(B2), "f"(B3)
                             : "memory");
            }
        }
        __syncthreads();
    }
}

// ============================================================================
// Kernel C: node post. Blocks own ONE species (skip weights staged in smem).
// ============================================================================
__global__ __launch_bounds__(256) void k_node(
    const float* __restrict__ nfs, const float* __restrict__ nfv,
    const float* __restrict__ Wds, const float* __restrict__ Wdv,
    const float* __restrict__ wsym_s, const float* __restrict__ wsym_v,
    const float* __restrict__ WLs, const float* __restrict__ WLv,
    const float* __restrict__ Wsk_s, const float* __restrict__ Wsk_v,
    const float* __restrict__ Wout,
    float* __restrict__ out0, float* __restrict__ fsO, float* __restrict__ fvO)
{
    extern __shared__ float sn[];
    float4* wd4  = (float4*)sn;
    float4* wl4  = (float4*)(sn + 8192);
    float4* sk4  = (float4*)(sn + 16384);
    float*  wsym = sn + 24576;
    float*  wout = sn + 24896;
    float4* aggb = (float4*)(sn + 24960);
    float4* nfb  = (float4*)(sn + 24960 + 8192);
    float4* psb  = (float4*)(sn + 24960 + 16384);

    int tid = threadIdx.x;
    int sp = blockIdx.y;

    {
        const float2* ds2 = (const float2*)Wds;
        const float2* dv2 = (const float2*)Wdv;
        const float2* ls2 = (const float2*)WLs;
        const float2* lv2 = (const float2*)WLv;
        const float2* ss2 = (const float2*)(Wsk_s + (size_t)sp * 4096);
        const float2* sv2 = (const float2*)(Wsk_v + (size_t)sp * 4096);
        for (int i = tid; i < 2048; i += 256) {
            float2 a = ds2[i], b = dv2[i];
            wd4[i] = make_float4(a.x, b.x, a.y, b.y);
            float2 cl = ls2[i], dl = lv2[i];
            wl4[i] = make_float4(cl.x, dl.x, cl.y, dl.y);
            float2 e = ss2[i], f = sv2[i];
            sk4[i] = make_float4(e.x, f.x, e.y, f.y);
        }
        for (int i = tid; i < 192; i += 256) wsym[i] = wsym_s[sp * 192 + i];
        for (int i = tid; i < 128; i += 256) wsym[192 + i] = wsym_v[sp * 128 + i];
        if (tid < 64) wout[tid] = Wout[tid];
    }
    __syncthreads();

    int warp = tid >> 5, lane = tid & 31;
    float4* ab = aggb + warp * 256;
    float4* nb = nfb + warp * 256;
    float4* pb = psb + warp * 256;
    int cnt = g_cnt[sp];
    const int* lst = g_bkt + sp * NN;
    const float* ws0 = wsym, *ws1 = wsym + 64, *ws2 = wsym + 128;
    const float* wv0 = wsym + 192, *wv1 = wsym + 256;

    for (int base = blockIdx.x * 32 + warp * 4; base < cnt; base += gridDim.x * 32) {
        int nv = cnt - base; if (nv > 4) nv = 4;
        int nn[4];
        #pragma unroll
        for (int j = 0; j < 4; j++) nn[j] = lst[base + ((j < nv) ? j : 0)];

        #pragma unroll
        for (int j = 0; j < 4; j++) {
            int n = nn[j];
            const float4* ga = (const float4*)g_A + (size_t)n * 64;
            ab[j * 64 + 2 * lane]     = ga[2 * lane];
            ab[j * 64 + 2 * lane + 1] = ga[2 * lane + 1];
            float2 sv = *(const float2*)(nfs + (size_t)n * 64 + 2 * lane);
            const float2* vp = (const float2*)(nfv + (size_t)n * 192);
            float2 p0 = vp[lane * 3], p1 = vp[lane * 3 + 1], p2 = vp[lane * 3 + 2];
            nb[j * 64 + 2 * lane]     = make_float4(sv.x, p0.x, p0.y, p1.x);
            nb[j * 64 + 2 * lane + 1] = make_float4(sv.y, p1.y, p2.x, p2.y);
        }
        __syncwarp();

        float acc[4][8];
        #pragma unroll
        for (int j = 0; j < 4; j++)
            #pragma unroll
            for (int q = 0; q < 8; q++) acc[j][q] = 0.f;

        #pragma unroll 4
        for (int f = 0; f < 64; f++) {
            float4 wq = wd4[f * 32 + lane];
            #pragma unroll
            for (int j = 0; j < 4; j++) {
                float4 a = ab[j * 64 + f];
                acc[j][0] = fmaf(a.x, wq.x, acc[j][0]);
                acc[j][1] = fmaf(a.y, wq.y, acc[j][1]);
                acc[j][2] = fmaf(a.z, wq.y, acc[j][2]);
                acc[j][3] = fmaf(a.w, wq.y, acc[j][3]);
                acc[j][4] = fmaf(a.x, wq.z, acc[j][4]);
                acc[j][5] = fmaf(a.y, wq.w, acc[j][5]);
                acc[j][6] = fmaf(a.z, wq.w, acc[j][6]);
                acc[j][7] = fmaf(a.w, wq.w, acc[j][7]);
            }
        }

        int c0 = 2 * lane, c1 = 2 * lane + 1;
        #pragma unroll
        for (int j = 0; j < 4; j++) {
            float sa0 = acc[j][0] * 0.25f, va0 = acc[j][1] * 0.25f;
            float va1 = acc[j][2] * 0.25f, va2 = acc[j][3] * 0.25f;
            float sa1 = acc[j][4] * 0.25f, vb0 = acc[j][5] * 0.25f;
            float vb1 = acc[j][6] * 0.25f, vb2 = acc[j][7] * 0.25f;
            float ps0 = ws0[c0] * sa0 + ws1[c0] * sa0 * sa0
                      + ws2[c0] * (va0 * va0 + va1 * va1 + va2 * va2);
            float cc0 = wv0[c0] + wv1[c0] * sa0;
            float ps1 = ws0[c1] * sa1 + ws1[c1] * sa1 * sa1
                      + ws2[c1] * (vb0 * vb0 + vb1 * vb1 + vb2 * vb2);
            float cc1 = wv0[c1] + wv1[c1] * sa1;
            pb[j * 64 + c0] = make_float4(ps0, cc0 * va0, cc0 * va1, cc0 * va2);
            pb[j * 64 + c1] = make_float4(ps1, cc1 * vb0, cc1 * vb1, cc1 * vb2);
        }
        __syncwarp();

        float a2c[4][8];
        #pragma unroll
        for (int j = 0; j < 4; j++)
            #pragma unroll
            for (int q = 0; q < 8; q++) a2c[j][q] = 0.f;

        #pragma unroll 4
        for (int f = 0; f < 64; f++) {
            float4 wl = wl4[f * 32 + lane];
            float4 sk = sk4[f * 32 + lane];
            #pragma unroll
            for (int j = 0; j < 4; j++) {
                float4 p = pb[j * 64 + f];
                float4 q = nb[j * 64 + f];
                a2c[j][0] = fmaf(p.x, wl.x, fmaf(q.x, sk.x, a2c[j][0]));
                a2c[j][1] = fmaf(p.y, wl.y, fmaf(q.y, sk.y, a2c[j][1]));
                a2c[j][2] = fmaf(p.z, wl.y, fmaf(q.z, sk.y, a2c[j][2]));
                a2c[j][3] = fmaf(p.w, wl.y, fmaf(q.w, sk.y, a2c[j][3]));
                a2c[j][4] = fmaf(p.x, wl.z, fmaf(q.x, sk.z, a2c[j][4]));
                a2c[j][5] = fmaf(p.y, wl.w, fmaf(q.y, sk.w, a2c[j][5]));
                a2c[j][6] = fmaf(p.z, wl.w, fmaf(q.z, sk.w, a2c[j][6]));
                a2c[j][7] = fmaf(p.w, wl.w, fmaf(q.w, sk.w, a2c[j][7]));
            }
        }

        #pragma unroll
        for (int j = 0; j < 4; j++) {
            int n = nn[j];
            float r = a2c[j][0] * wout[c0] + a2c[j][4] * wout[c1];
            #pragma unroll
            for (int off = 16; off > 0; off >>= 1)
                r += __shfl_xor_sync(0xffffffffu, r, off);
            if (j < nv) {
                *(float2*)(fsO + (size_t)n * 64 + c0) = make_float2(a2c[j][0], a2c[j][4]);
                float* vb = fvO + (size_t)n * 192 + 6 * lane;
                *(float2*)(vb)     = make_float2(a2c[j][1], a2c[j][2]);
                *(float2*)(vb + 2) = make_float2(a2c[j][3], a2c[j][5]);
                *(float2*)(vb + 4) = make_float2(a2c[j][6], a2c[j][7]);
                if (lane == 0) out0[n] = r;
            }
        }
        __syncwarp();
    }
}

// ============================================================================
extern "C" void kernel_launch(void* const* d_in, const int* in_sizes, int n_in,
                              void* d_out, int out_size)
{
    const float* vectors  = (const float*)d_in[0];
    const float* nfs      = (const float*)d_in[1];
    const float* nfv      = (const float*)d_in[2];
    const float* RE       = (const float*)d_in[3];
    const float* Wus      = (const float*)d_in[4];
    const float* Wuv      = (const float*)d_in[5];
    const float* Wr1      = (const float*)d_in[6];
    const float* Wr2      = (const float*)d_in[7];
    const float* Wds      = (const float*)d_in[8];
    const float* Wdv      = (const float*)d_in[9];
    const float* wsym_s   = (const float*)d_in[10];
    const float* wsym_v   = (const float*)d_in[11];
    const float* WLs      = (const float*)d_in[12];
    const float* WLv      = (const float*)d_in[13];
    const float* Wsk_s    = (const float*)d_in[14];
    const float* Wsk_v    = (const float*)d_in[15];
    const float* Wout     = (const float*)d_in[16];
    const int*   specie   = (const int*)d_in[17];
    const int*   senders  = (const int*)d_in[18];
    const int*   receivers= (const int*)d_in[19];

    int N = in_sizes[1] / 64;
    int E = in_sizes[18];
    if (N > NN) N = NN;
    if (E > EE) E = EE;

    float* out0 = (float*)d_out;
    float* fsO  = out0 + N;
    float* fvO  = fsO + (size_t)N * 64;

    const int UP_SMEM   = (8192 + 2048 + 8192) * 4;                 // 73728 B
    const int EDGE_SMEM = (20992 + 20992 + 4352 + 512 + 512) * 4;   // 189440 B
    const int NODE_SMEM = (24960 + 3 * 8192) * 4;                   // 198144 B
    cudaFuncSetAttribute(k_up,   cudaFuncAttributeMaxDynamicSharedMemorySize, UP_SMEM);
    cudaFuncSetAttribute(k_edge, cudaFuncAttributeMaxDynamicSharedMemorySize, EDGE_SMEM);
    cudaFuncSetAttribute(k_node, cudaFuncAttributeMaxDynamicSharedMemorySize, NODE_SMEM);

    // receiver counting sort
    k_zero_deg<<<(N + 255) / 256, 256>>>(N);
    k_hist<<<(E + 255) / 256, 256>>>(receivers, E);
    k_scan<<<1, 1024>>>(N);
    k_scatter<<<(E + 255) / 256, 256>>>(receivers, E);

    // species bucketing
    k_zero_cnt<<<1, 32>>>();
    k_bucket<<<(N + 255) / 256, 256>>>(specie, N);

    k_up<<<296, 256, UP_SMEM>>>(nfs, nfv, Wus, Wuv, N);
    k_edge<<<148, 256, EDGE_SMEM>>>(RE, Wr1, Wr2, vectors, senders, receivers, E);
    k_node<<<dim3(15, NSPEC), 256, NODE_SMEM>>>(nfs, nfv, Wds, Wdv,
                                                wsym_s, wsym_v, WLs, WLv,
                                                Wsk_s, Wsk_v, Wout,
                                                out0, fsO, fvO);
}

// round 8
// speedup vs baseline: 1.6418x; 1.6418x over previous
#include <cuda_runtime.h>
#include <math.h>

#define NN 50000
#define EE 800000
#define NSPEC 10

// ---- scratch (static device globals; allocation-free) ----
__device__ float g_S[NN * 64];          // up-projected scalars [N,64]
__device__ float g_V[NN * 192];         // up-projected vectors [N,64,3]
__device__ float g_A[NN * 256];         // packed aggregation [N][64][4] = (s,vx,vy,vz)
__device__ int   g_cnt[16];             // per-species node counts
__device__ int   g_bkt[NSPEC * NN];     // per-species node lists

__device__ __forceinline__ unsigned f2tf32(float x) {
    unsigned r;
    asm("cvt.rna.tf32.f32 %0, %1;" : "=r"(r) : "f"(x));
    return r;
}

// ============================================================================
// Species bucketing (warp-aggregated)
// ============================================================================
__global__ void k_zero_cnt() { if (threadIdx.x < 16) g_cnt[threadIdx.x] = 0; }

__global__ __launch_bounds__(256) void k_bucket(const int* __restrict__ specie, int N)
{
    int i = blockIdx.x * blockDim.x + threadIdx.x;
    if (i < N) {
        int sp = specie[i];
        unsigned mask = __match_any_sync(__activemask(), sp);
        int lane = threadIdx.x & 31;
        int leader = __ffs(mask) - 1;
        int rank = __popc(mask & ((1u << lane) - 1));
        int base = 0;
        if (lane == leader) base = atomicAdd(&g_cnt[sp], __popc(mask));
        base = __shfl_sync(mask, base, leader);
        g_bkt[sp * NN + base + rank] = i;
    }
}

// ============================================================================
// Kernel A: linear-up + zero packed aggregation buffer.
// ============================================================================
__global__ __launch_bounds__(256) void k_up(
    const float* __restrict__ nfs, const float* __restrict__ nfv,
    const float* __restrict__ Wus, const float* __restrict__ Wuv, int N)
{
    extern __shared__ float su[];
    float4* wsv4 = (float4*)su;
    float*  s_in = su + 8192;
    float4* v_in = (float4*)(su + 8192 + 2048);

    int tid = threadIdx.x;
    const float2* us2 = (const float2*)Wus;
    const float2* uv2 = (const float2*)Wuv;
    for (int i = tid; i < 2048; i += 256) {
        float2 a = us2[i], b = uv2[i];
        wsv4[i] = make_float4(a.x, b.x, a.y, b.y);
    }
    __syncthreads();

    int warp = tid >> 5, lane = tid & 31;
    float*  ss = s_in + warp * 256;
    float4* vv = v_in + warp * 256;

    for (int base = blockIdx.x * 32 + warp * 4; base < N; base += gridDim.x * 32) {
        int nv = N - base; if (nv > 4) nv = 4;
        #pragma unroll
        for (int j = 0; j < 4; j++) {
            if (j < nv) {
                int n = base + j;
                float2 sv = *(const float2*)(nfs + (size_t)n * 64 + 2 * lane);
                ss[j * 64 + 2 * lane]     = sv.x;
                ss[j * 64 + 2 * lane + 1] = sv.y;
                const float2* vp = (const float2*)(nfv + (size_t)n * 192);
                float2 p0 = vp[lane * 3], p1 = vp[lane * 3 + 1], p2 = vp[lane * 3 + 2];
                vv[j * 64 + 2 * lane]     = make_float4(p0.x, p0.y, p1.x, 0.f);
                vv[j * 64 + 2 * lane + 1] = make_float4(p1.y, p2.x, p2.y, 0.f);
            }
        }
        __syncwarp();

        float acc[4][8];
        #pragma unroll
        for (int j = 0; j < 4; j++)
            #pragma unroll
            for (int q = 0; q < 8; q++) acc[j][q] = 0.f;

        #pragma unroll 4
        for (int f = 0; f < 64; f++) {
            float4 wq = wsv4[f * 32 + lane];
            #pragma unroll
            for (int j = 0; j < 4; j++) {
                float  sb = ss[j * 64 + f];
                float4 vb = vv[j * 64 + f];
                acc[j][0] = fmaf(sb, wq.x, acc[j][0]);
                acc[j][1] = fmaf(sb, wq.z, acc[j][1]);
                acc[j][2] = fmaf(vb.x, wq.y, acc[j][2]);
                acc[j][3] = fmaf(vb.y, wq.y, acc[j][3]);
                acc[j][4] = fmaf(vb.z, wq.y, acc[j][4]);
                acc[j][5] = fmaf(vb.x, wq.w, acc[j][5]);
                acc[j][6] = fmaf(vb.y, wq.w, acc[j][6]);
                acc[j][7] = fmaf(vb.z, wq.w, acc[j][7]);
            }
        }

        for (int j = 0; j < nv; j++) {
            int n = base + j;
            *(float2*)(g_S + (size_t)n * 64 + 2 * lane) = make_float2(acc[j][0], acc[j][1]);
            float2* vp = (float2*)(g_V + (size_t)n * 192);
            vp[lane * 3]     = make_float2(acc[j][2], acc[j][3]);
            vp[lane * 3 + 1] = make_float2(acc[j][4], acc[j][5]);
            vp[lane * 3 + 2] = make_float2(acc[j][6], acc[j][7]);
            float4* za = (float4*)(g_A + (size_t)n * 256);
            za[lane]      = make_float4(0.f, 0.f, 0.f, 0.f);
            za[32 + lane] = make_float4(0.f, 0.f, 0.f, 0.f);
        }
        __syncwarp();
    }
}

// ============================================================================
// Kernel B (warp-specialized pipeline): 512 threads.
//   warps 0-7  (producers): radial MLP (tf32 MMA) for tile t  -> csm[p]
//   warps 8-15 (consumers): messages + atomic scatter for tile t-1 from csm[1-p]
// Tile = 32 edges. Double-buffered C. One __syncthreads per iteration.
// ============================================================================
__global__ __launch_bounds__(512) void k_edge(
    const float* __restrict__ RE, const float* __restrict__ Wr1,
    const float* __restrict__ Wr2, const float* __restrict__ vectors,
    const int* __restrict__ senders, const int* __restrict__ receivers, int En)
{
    extern __shared__ float sg[];
    unsigned* wr2u = (unsigned*)sg;                 // 64*328 = 20992
    float*    csm  = sg + 20992;                    // 2 * 32*328 = 20992
    unsigned* hu   = (unsigned*)(sg + 41984);       // 32*68 = 2176
    float*    res  = sg + 41984 + 2176;             // 256
    float*    wr1s = res + 256;                     // 512
    // total 44928 floats = 179712 B

    int tid = threadIdx.x;
    for (int i = tid; i < 20480; i += 512) {
        int j = i / 320, n = i - j * 320;
        wr2u[j * 328 + n] = f2tf32(Wr2[i]);
    }
    for (int i = tid; i < 512; i += 512) wr1s[i] = Wr1[i];
    __syncthreads();

    int lane = tid & 31, warp = tid >> 5;
    int gid = lane >> 2, tig = lane & 3;
    bool producer = (warp < 8);
    int ntiles = (En + 31) >> 5;
    int gd = gridDim.x;
    int p = 0;

    for (int it = 0; ; it++) {
        int tP = blockIdx.x + it * gd;
        int tC = tP - gd;
        if (tC >= ntiles) break;
        float* bufP = csm + p * 10496;
        float* bufC = csm + (1 - p) * 10496;

        if (producer && tP < ntiles) {
            int e0 = tP << 5;
            // stage RE tile (1 float per producer thread)
            {
                int el = tid >> 3;
                int e = e0 + el;
                res[tid] = (e < En) ? __ldg(RE + (size_t)e * 8 + (tid & 7)) : 0.f;
            }
            asm volatile("bar.sync 1, 256;" ::: "memory");
            // h = silu(res @ W_r1) as tf32  (2048 outputs / 256 threads)
            #pragma unroll
            for (int i = 0; i < 8; i++) {
                int idx = tid + 256 * i;
                int e = idx >> 6, j = idx & 63;
                const float* rr = res + e * 8;
                float a = 0.f;
                #pragma unroll
                for (int k = 0; k < 8; k++) a = fmaf(rr[k], wr1s[k * 64 + j], a);
                hu[e * 68 + j] = f2tf32(__fdividef(a, 1.f + __expf(-a)));
            }
            asm volatile("bar.sync 1, 256;" ::: "memory");

            // MMA: C[32,320] = h @ W_r2, warp owns a 40-col strip
            float c[2][5][4];
            #pragma unroll
            for (int mt = 0; mt < 2; mt++)
                #pragma unroll
                for (int nt = 0; nt < 5; nt++)
                    #pragma unroll
                    for (int q = 0; q < 4; q++) c[mt][nt][q] = 0.f;

            #pragma unroll
            for (int ks = 0; ks < 8; ks++) {
                int kb = ks * 8;
                unsigned a[2][4];
                #pragma unroll
                for (int mt = 0; mt < 2; mt++) {
                    int r0 = mt * 16 + gid;
                    a[mt][0] = hu[r0 * 68 + kb + tig];
                    a[mt][1] = hu[(r0 + 8) * 68 + kb + tig];
                    a[mt][2] = hu[r0 * 68 + kb + tig + 4];
                    a[mt][3] = hu[(r0 + 8) * 68 + kb + tig + 4];
                }
                #pragma unroll
                for (int nt = 0; nt < 5; nt++) {
                    int col = warp * 40 + nt * 8 + gid;
                    unsigned b0 = wr2u[(kb + tig) * 328 + col];
                    unsigned b1 = wr2u[(kb + tig + 4) * 328 + col];
                    #pragma unroll
                    for (int mt = 0; mt < 2; mt++) {
                        asm volatile(
                            "mma.sync.aligned.m16n8k8.row.col.f32.tf32.tf32.f32 "
                            "{%0,%1,%2,%3}, {%4,%5,%6,%7}, {%8,%9}, {%0,%1,%2,%3};\n"
                            : "+f"(c[mt][nt][0]), "+f"(c[mt][nt][1]),
                              "+f"(c[mt][nt][2]), "+f"(c[mt][nt][3])
                            : "r"(a[mt][0]), "r"(a[mt][1]), "r"(a[mt][2]), "r"(a[mt][3]),
                              "r"(b0), "r"(b1));
                    }
                }
            }
            // store C fragments into bufP
            #pragma unroll
            for (int mt = 0; mt < 2; mt++) {
                int r0 = mt * 16 + gid;
                #pragma unroll
                for (int nt = 0; nt < 5; nt++) {
                    int col = warp * 40 + nt * 8 + 2 * tig;
                    *(float2*)(bufP + r0 * 328 + col) = make_float2(c[mt][nt][0], c[mt][nt][1]);
                    *(float2*)(bufP + (r0 + 8) * 328 + col) = make_float2(c[mt][nt][2], c[mt][nt][3]);
                }
            }
        }

        if (!producer && tC >= 0) {
            int e0 = tC << 5;
            int cw = warp - 8;
            #pragma unroll
            for (int i = 0; i < 4; i++) {
                int el = cw * 4 + i;
                int e = e0 + el;
                if (e < En) {
                    const float* cwp = bufC + el * 328;
                    float2 w0 = *(const float2*)(cwp + 2 * lane);
                    float2 w1 = *(const float2*)(cwp + 64 + 2 * lane);
                    float2 w2 = *(const float2*)(cwp + 128 + 2 * lane);
                    float2 w3 = *(const float2*)(cwp + 192 + 2 * lane);
                    float2 w4 = *(const float2*)(cwp + 256 + 2 * lane);

                    int s = __ldg(senders + e);
                    int r = __ldg(receivers + e);
                    float vx = __ldg(vectors + (size_t)e * 3 + 0);
                    float vy = __ldg(vectors + (size_t)e * 3 + 1);
                    float vz = __ldg(vectors + (size_t)e * 3 + 2);
                    float nrm = sqrtf(vx * vx + vy * vy + vz * vz);
                    float ri = 1.f / (nrm + 1e-9f);
                    float Y0 = vx * ri, Y1 = vy * ri, Y2 = vz * ri;

                    float2 xs = __ldg((const float2*)(g_S + (size_t)s * 64) + lane);
                    const float2* Vp = (const float2*)(g_V + (size_t)s * 192);
                    float2 p0 = __ldg(Vp + lane * 3 + 0);
                    float2 p1 = __ldg(Vp + lane * 3 + 1);
                    float2 p2 = __ldg(Vp + lane * 3 + 2);
                    float a0 = p0.x, a1 = p0.y, a2 = p1.x;
                    float b0 = p1.y, b1 = p2.x, b2 = p2.y;

                    float dota = a0 * Y0 + a1 * Y1 + a2 * Y2;
                    float dotb = b0 * Y0 + b1 * Y1 + b2 * Y2;

                    float msa = w0.x * xs.x + w3.x * dota;
                    float msb = w0.y * xs.y + w3.y * dotb;

                    float cxa0 = a1 * Y2 - a2 * Y1;
                    float cxa1 = a2 * Y0 - a0 * Y2;
                    float cxa2 = a0 * Y1 - a1 * Y0;
                    float cxb0 = b1 * Y2 - b2 * Y1;
                    float cxb1 = b2 * Y0 - b0 * Y2;
                    float cxb2 = b0 * Y1 - b1 * Y0;

                    float sa = w1.x * xs.x, sb = w1.y * xs.y;
                    float mva0 = sa * Y0 + w2.x * a0 + w4.x * cxa0;
                    float mva1 = sa * Y1 + w2.x * a1 + w4.x * cxa1;
                    float mva2 = sa * Y2 + w2.x * a2 + w4.x * cxa2;
                    float mvb0 = sb * Y0 + w2.y * b0 + w4.y * cxb0;
                    float mvb1 = sb * Y1 + w2.y * b1 + w4.y * cxb1;
                    float mvb2 = sb * Y2 + w2.y * b2 + w4.y * cxb2;

                    float* base = g_A + (size_t)r * 256 + lane * 8;
                    asm volatile("red.global.add.v4.f32 [%0], {%1,%2,%3,%4};"
                                 :: "l"(base), "f"(msa), "f"(mva0), "f"(mva1), "f"(mva2)
                                 : "memory");
                    asm volatile("red.global.add.v4.f32 [%0], {%1,%2,%3,%4};"
                                 :: "l"(base + 4), "f"(msb), "f"(mvb0), "f"(mvb1), "f"(mvb2)
                                 : "memory");
                }
            }
        }
        __syncthreads();
        p ^= 1;
    }
}

// ============================================================================
// Kernel C: node post. Blocks own ONE species (skip weights staged in smem).
// ============================================================================
__global__ __launch_bounds__(256) void k_node(
    const float* __restrict__ nfs, const float* __restrict__ nfv,
    const float* __restrict__ Wds, const float* __restrict__ Wdv,
    const float* __restrict__ wsym_s, const float* __restrict__ wsym_v,
    const float* __restrict__ WLs, const float* __restrict__ WLv,
    const float* __restrict__ Wsk_s, const float* __restrict__ Wsk_v,
    const float* __restrict__ Wout,
    float* __restrict__ out0, float* __restrict__ fsO, float* __restrict__ fvO)
{
    extern __shared__ float sn[];
    float4* wd4  = (float4*)sn;
    float4* wl4  = (float4*)(sn + 8192);
    float4* sk4  = (float4*)(sn + 16384);
    float*  wsym = sn + 24576;
    float*  wout = sn + 24896;
    float4* aggb = (float4*)(sn + 24960);
    float4* nfb  = (float4*)(sn + 24960 + 8192);
    float4* psb  = (float4*)(sn + 24960 + 16384);

    int tid = threadIdx.x;
    int sp = blockIdx.y;

    {
        const float2* ds2 = (const float2*)Wds;
        const float2* dv2 = (const float2*)Wdv;
        const float2* ls2 = (const float2*)WLs;
        const float2* lv2 = (const float2*)WLv;
        const float2* ss2 = (const float2*)(Wsk_s + (size_t)sp * 4096);
        const float2* sv2 = (const float2*)(Wsk_v + (size_t)sp * 4096);
        for (int i = tid; i < 2048; i += 256) {
            float2 a = ds2[i], b = dv2[i];
            wd4[i] = make_float4(a.x, b.x, a.y, b.y);
            float2 cl = ls2[i], dl = lv2[i];
            wl4[i] = make_float4(cl.x, dl.x, cl.y, dl.y);
            float2 e = ss2[i], f = sv2[i];
            sk4[i] = make_float4(e.x, f.x, e.y, f.y);
        }
        for (int i = tid; i < 192; i += 256) wsym[i] = wsym_s[sp * 192 + i];
        for (int i = tid; i < 128; i += 256) wsym[192 + i] = wsym_v[sp * 128 + i];
        if (tid < 64) wout[tid] = Wout[tid];
    }
    __syncthreads();

    int warp = tid >> 5, lane = tid & 31;
    float4* ab = aggb + warp * 256;
    float4* nb = nfb + warp * 256;
    float4* pb = psb + warp * 256;
    int cnt = g_cnt[sp];
    const int* lst = g_bkt + sp * NN;
    const float* ws0 = wsym, *ws1 = wsym + 64, *ws2 = wsym + 128;
    const float* wv0 = wsym + 192, *wv1 = wsym + 256;

    for (int base = blockIdx.x * 32 + warp * 4; base < cnt; base += gridDim.x * 32) {
        int nv = cnt - base; if (nv > 4) nv = 4;
        int nn[4];
        #pragma unroll
        for (int j = 0; j < 4; j++) nn[j] = lst[base + ((j < nv) ? j : 0)];

        #pragma unroll
        for (int j = 0; j < 4; j++) {
            int n = nn[j];
            const float4* ga = (const float4*)g_A + (size_t)n * 64;
            ab[j * 64 + 2 * lane]     = ga[2 * lane];
            ab[j * 64 + 2 * lane + 1] = ga[2 * lane + 1];
            float2 sv = *(const float2*)(nfs + (size_t)n * 64 + 2 * lane);
            const float2* vp = (const float2*)(nfv + (size_t)n * 192);
            float2 p0 = vp[lane * 3], p1 = vp[lane * 3 + 1], p2 = vp[lane * 3 + 2];
            nb[j * 64 + 2 * lane]     = make_float4(sv.x, p0.x, p0.y, p1.x);
            nb[j * 64 + 2 * lane + 1] = make_float4(sv.y, p1.y, p2.x, p2.y);
        }
        __syncwarp();

        float acc[4][8];
        #pragma unroll
        for (int j = 0; j < 4; j++)
            #pragma unroll
            for (int q = 0; q < 8; q++) acc[j][q] = 0.f;

        #pragma unroll 4
        for (int f = 0; f < 64; f++) {
            float4 wq = wd4[f * 32 + lane];
            #pragma unroll
            for (int j = 0; j < 4; j++) {
                float4 a = ab[j * 64 + f];
                acc[j][0] = fmaf(a.x, wq.x, acc[j][0]);
                acc[j][1] = fmaf(a.y, wq.y, acc[j][1]);
                acc[j][2] = fmaf(a.z, wq.y, acc[j][2]);
                acc[j][3] = fmaf(a.w, wq.y, acc[j][3]);
                acc[j][4] = fmaf(a.x, wq.z, acc[j][4]);
                acc[j][5] = fmaf(a.y, wq.w, acc[j][5]);
                acc[j][6] = fmaf(a.z, wq.w, acc[j][6]);
                acc[j][7] = fmaf(a.w, wq.w, acc[j][7]);
            }
        }

        int c0 = 2 * lane, c1 = 2 * lane + 1;
        #pragma unroll
        for (int j = 0; j < 4; j++) {
            float sa0 = acc[j][0] * 0.25f, va0 = acc[j][1] * 0.25f;
            float va1 = acc[j][2] * 0.25f, va2 = acc[j][3] * 0.25f;
            float sa1 = acc[j][4] * 0.25f, vb0 = acc[j][5] * 0.25f;
            float vb1 = acc[j][6] * 0.25f, vb2 = acc[j][7] * 0.25f;
            float ps0 = ws0[c0] * sa0 + ws1[c0] * sa0 * sa0
                      + ws2[c0] * (va0 * va0 + va1 * va1 + va2 * va2);
            float cc0 = wv0[c0] + wv1[c0] * sa0;
            float ps1 = ws0[c1] * sa1 + ws1[c1] * sa1 * sa1
                      + ws2[c1] * (vb0 * vb0 + vb1 * vb1 + vb2 * vb2);
            float cc1 = wv0[c1] + wv1[c1] * sa1;
            pb[j * 64 + c0] = make_float4(ps0, cc0 * va0, cc0 * va1, cc0 * va2);
            pb[j * 64 + c1] = make_float4(ps1, cc1 * vb0, cc1 * vb1, cc1 * vb2);
        }
        __syncwarp();

        float a2c[4][8];
        #pragma unroll
        for (int j = 0; j < 4; j++)
            #pragma unroll
            for (int q = 0; q < 8; q++) a2c[j][q] = 0.f;

        #pragma unroll 4
        for (int f = 0; f < 64; f++) {
            float4 wl = wl4[f * 32 + lane];
            float4 sk = sk4[f * 32 + lane];
            #pragma unroll
            for (int j = 0; j < 4; j++) {
                float4 p = pb[j * 64 + f];
                float4 q = nb[j * 64 + f];
                a2c[j][0] = fmaf(p.x, wl.x, fmaf(q.x, sk.x, a2c[j][0]));
                a2c[j][1] = fmaf(p.y, wl.y, fmaf(q.y, sk.y, a2c[j][1]));
                a2c[j][2] = fmaf(p.z, wl.y, fmaf(q.z, sk.y, a2c[j][2]));
                a2c[j][3] = fmaf(p.w, wl.y, fmaf(q.w, sk.y, a2c[j][3]));
                a2c[j][4] = fmaf(p.x, wl.z, fmaf(q.x, sk.z, a2c[j][4]));
                a2c[j][5] = fmaf(p.y, wl.w, fmaf(q.y, sk.w, a2c[j][5]));
                a2c[j][6] = fmaf(p.z, wl.w, fmaf(q.z, sk.w, a2c[j][6]));
                a2c[j][7] = fmaf(p.w, wl.w, fmaf(q.w, sk.w, a2c[j][7]));
            }
        }

        #pragma unroll
        for (int j = 0; j < 4; j++) {
            int n = nn[j];
            float r = a2c[j][0] * wout[c0] + a2c[j][4] * wout[c1];
            #pragma unroll
            for (int off = 16; off > 0; off >>= 1)
                r += __shfl_xor_sync(0xffffffffu, r, off);
            if (j < nv) {
                *(float2*)(fsO + (size_t)n * 64 + c0) = make_float2(a2c[j][0], a2c[j][4]);
                float* vb = fvO + (size_t)n * 192 + 6 * lane;
                *(float2*)(vb)     = make_float2(a2c[j][1], a2c[j][2]);
                *(float2*)(vb + 2) = make_float2(a2c[j][3], a2c[j][5]);
                *(float2*)(vb + 4) = make_float2(a2c[j][6], a2c[j][7]);
                if (lane == 0) out0[n] = r;
            }
        }
        __syncwarp();
    }
}

// ============================================================================
extern "C" void kernel_launch(void* const* d_in, const int* in_sizes, int n_in,
                              void* d_out, int out_size)
{
    const float* vectors  = (const float*)d_in[0];
    const float* nfs      = (const float*)d_in[1];
    const float* nfv      = (const float*)d_in[2];
    const float* RE       = (const float*)d_in[3];
    const float* Wus      = (const float*)d_in[4];
    const float* Wuv      = (const float*)d_in[5];
    const float* Wr1      = (const float*)d_in[6];
    const float* Wr2      = (const float*)d_in[7];
    const float* Wds      = (const float*)d_in[8];
    const float* Wdv      = (const float*)d_in[9];
    const float* wsym_s   = (const float*)d_in[10];
    const float* wsym_v   = (const float*)d_in[11];
    const float* WLs      = (const float*)d_in[12];
    const float* WLv      = (const float*)d_in[13];
    const float* Wsk_s    = (const float*)d_in[14];
    const float* Wsk_v    = (const float*)d_in[15];
    const float* Wout     = (const float*)d_in[16];
    const int*   specie   = (const int*)d_in[17];
    const int*   senders  = (const int*)d_in[18];
    const int*   receivers= (const int*)d_in[19];

    int N = in_sizes[1] / 64;
    int E = in_sizes[18];
    if (N > NN) N = NN;
    if (E > EE) E = EE;

    float* out0 = (float*)d_out;
    float* fsO  = out0 + N;
    float* fvO  = fsO + (size_t)N * 64;

    const int UP_SMEM   = (8192 + 2048 + 8192) * 4;                 // 73728 B
    const int EDGE_SMEM = 44928 * 4;                                // 179712 B
    const int NODE_SMEM = (24960 + 3 * 8192) * 4;                   // 198144 B
    cudaFuncSetAttribute(k_up,   cudaFuncAttributeMaxDynamicSharedMemorySize, UP_SMEM);
    cudaFuncSetAttribute(k_edge, cudaFuncAttributeMaxDynamicSharedMemorySize, EDGE_SMEM);
    cudaFuncSetAttribute(k_node, cudaFuncAttributeMaxDynamicSharedMemorySize, NODE_SMEM);

    // species bucketing
    k_zero_cnt<<<1, 32>>>();
    k_bucket<<<(N + 255) / 256, 256>>>(specie, N);

    k_up<<<296, 256, UP_SMEM>>>(nfs, nfv, Wus, Wuv, N);
    k_edge<<<148, 512, EDGE_SMEM>>>(RE, Wr1, Wr2, vectors, senders, receivers, E);
    k_node<<<dim3(15, NSPEC), 256, NODE_SMEM>>>(nfs, nfv, Wds, Wdv,
                                                wsym_s, wsym_v, WLs, WLv,
                                                Wsk_s, Wsk_v, Wout,
                                                out0, fsO, fvO);
}

// round 9
// speedup vs baseline: 2.1638x; 1.3179x over previous
#include <cuda_runtime.h>
#include <cuda_fp16.h>
#include <math.h>

#define NN 50000
#define EE 800000
#define NSPEC 10

// ---- scratch (static device globals; allocation-free) ----
__device__ float g_S[NN * 64];          // up-projected scalars [N,64]
__device__ float g_V[NN * 192];         // up-projected vectors [N,64,3]
__device__ float g_A[NN * 256];         // packed aggregation [N][64][4] = (s,vx,vy,vz)
__device__ int   g_cnt[16];             // per-species node counts
__device__ int   g_bkt[NSPEC * NN];     // per-species node lists

// ============================================================================
// Species bucketing (warp-aggregated)
// ============================================================================
__global__ void k_zero_cnt() { if (threadIdx.x < 16) g_cnt[threadIdx.x] = 0; }

__global__ __launch_bounds__(256) void k_bucket(const int* __restrict__ specie, int N)
{
    int i = blockIdx.x * blockDim.x + threadIdx.x;
    if (i < N) {
        int sp = specie[i];
        unsigned mask = __match_any_sync(__activemask(), sp);
        int lane = threadIdx.x & 31;
        int leader = __ffs(mask) - 1;
        int rank = __popc(mask & ((1u << lane) - 1));
        int base = 0;
        if (lane == leader) base = atomicAdd(&g_cnt[sp], __popc(mask));
        base = __shfl_sync(mask, base, leader);
        g_bkt[sp * NN + base + rank] = i;
    }
}

// ============================================================================
// Kernel A: linear-up + zero packed aggregation buffer.
// ============================================================================
__global__ __launch_bounds__(256) void k_up(
    const float* __restrict__ nfs, const float* __restrict__ nfv,
    const float* __restrict__ Wus, const float* __restrict__ Wuv, int N)
{
    extern __shared__ float su[];
    float4* wsv4 = (float4*)su;
    float*  s_in = su + 8192;
    float4* v_in = (float4*)(su + 8192 + 2048);

    int tid = threadIdx.x;
    const float2* us2 = (const float2*)Wus;
    const float2* uv2 = (const float2*)Wuv;
    for (int i = tid; i < 2048; i += 256) {
        float2 a = us2[i], b = uv2[i];
        wsv4[i] = make_float4(a.x, b.x, a.y, b.y);
    }
    __syncthreads();

    int warp = tid >> 5, lane = tid & 31;
    float*  ss = s_in + warp * 256;
    float4* vv = v_in + warp * 256;

    for (int base = blockIdx.x * 32 + warp * 4; base < N; base += gridDim.x * 32) {
        int nv = N - base; if (nv > 4) nv = 4;
        #pragma unroll
        for (int j = 0; j < 4; j++) {
            if (j < nv) {
                int n = base + j;
                float2 sv = *(const float2*)(nfs + (size_t)n * 64 + 2 * lane);
                ss[j * 64 + 2 * lane]     = sv.x;
                ss[j * 64 + 2 * lane + 1] = sv.y;
                const float2* vp = (const float2*)(nfv + (size_t)n * 192);
                float2 p0 = vp[lane * 3], p1 = vp[lane * 3 + 1], p2 = vp[lane * 3 + 2];
                vv[j * 64 + 2 * lane]     = make_float4(p0.x, p0.y, p1.x, 0.f);
                vv[j * 64 + 2 * lane + 1] = make_float4(p1.y, p2.x, p2.y, 0.f);
            }
        }
        __syncwarp();

        float acc[4][8];
        #pragma unroll
        for (int j = 0; j < 4; j++)
            #pragma unroll
            for (int q = 0; q < 8; q++) acc[j][q] = 0.f;

        #pragma unroll 4
        for (int f = 0; f < 64; f++) {
            float4 wq = wsv4[f * 32 + lane];
            #pragma unroll
            for (int j = 0; j < 4; j++) {
                float  sb = ss[j * 64 + f];
                float4 vb = vv[j * 64 + f];
                acc[j][0] = fmaf(sb, wq.x, acc[j][0]);
                acc[j][1] = fmaf(sb, wq.z, acc[j][1]);
                acc[j][2] = fmaf(vb.x, wq.y, acc[j][2]);
                acc[j][3] = fmaf(vb.y, wq.y, acc[j][3]);
                acc[j][4] = fmaf(vb.z, wq.y, acc[j][4]);
                acc[j][5] = fmaf(vb.x, wq.w, acc[j][5]);
                acc[j][6] = fmaf(vb.y, wq.w, acc[j][6]);
                acc[j][7] = fmaf(vb.z, wq.w, acc[j][7]);
            }
        }

        for (int j = 0; j < nv; j++) {
            int n = base + j;
            *(float2*)(g_S + (size_t)n * 64 + 2 * lane) = make_float2(acc[j][0], acc[j][1]);
            float2* vp = (float2*)(g_V + (size_t)n * 192);
            vp[lane * 3]     = make_float2(acc[j][2], acc[j][3]);
            vp[lane * 3 + 1] = make_float2(acc[j][4], acc[j][5]);
            vp[lane * 3 + 2] = make_float2(acc[j][6], acc[j][7]);
            float4* za = (float4*)(g_A + (size_t)n * 256);
            za[lane]      = make_float4(0.f, 0.f, 0.f, 0.f);
            za[32 + lane] = make_float4(0.f, 0.f, 0.f, 0.f);
        }
        __syncwarp();
    }
}

// ============================================================================
// Kernel B (warp-specialized pipeline, fp16 MMA): 512 threads, 2 blocks/SM.
//   warps 0-7  (producers): radial MLP (fp16 m16n8k16 MMA) tile t -> csm[p] (fp16)
//   warps 8-15 (consumers): messages + atomic scatter tile t-1 from csm[1-p]
// Tile = 32 edges. W_r2 in smem fp16 transposed [n][j] stride 72 (conflict-free).
// ============================================================================
__global__ __launch_bounds__(512, 2) void k_edge(
    const float* __restrict__ RE, const float* __restrict__ Wr1,
    const float* __restrict__ Wr2, const float* __restrict__ vectors,
    const int* __restrict__ senders, const int* __restrict__ receivers, int En)
{
    extern __shared__ float sg[];
    __half* wr2t = (__half*)sg;                     // [320][72] halfs -> 11520 floats
    __half* csmH = (__half*)(sg + 11520);           // 2 * 32*328 halfs -> 10496 floats
    __half* hu   = (__half*)(sg + 22016);           // [32][72] halfs -> 1152 floats
    float*  res  = sg + 23168;                      // 256
    float*  wr1s = res + 256;                       // 512
    // total 23936 floats = 95744 B

    int tid = threadIdx.x;
    // stage W_r2 transposed: wr2t[n][j] = Wr2[j][n]
    for (int i = tid; i < 20480; i += 512) {
        int j = i / 320, n = i - j * 320;
        wr2t[n * 72 + j] = __float2half_rn(Wr2[i]);
    }
    for (int i = tid; i < 512; i += 512) wr1s[i] = Wr1[i];
    __syncthreads();

    int lane = tid & 31, warp = tid >> 5;
    int gid = lane >> 2, tig = lane & 3;
    bool producer = (warp < 8);
    int ntiles = (En + 31) >> 5;
    int gd = gridDim.x;
    int p = 0;

    for (int it = 0; ; it++) {
        int tP = blockIdx.x + it * gd;
        int tC = tP - gd;
        if (tC >= ntiles) break;
        __half* bufP = csmH + p * 10496;
        __half* bufC = csmH + (1 - p) * 10496;

        if (producer && tP < ntiles) {
            int e0 = tP << 5;
            // stage RE tile (1 float per producer thread)
            {
                int el = tid >> 3;
                int e = e0 + el;
                res[tid] = (e < En) ? __ldg(RE + (size_t)e * 8 + (tid & 7)) : 0.f;
            }
            asm volatile("bar.sync 1, 256;" ::: "memory");
            // h = silu(res @ W_r1), two adjacent j per thread -> half2 store
            #pragma unroll
            for (int i = 0; i < 4; i++) {
                int idx = tid + 256 * i;        // 0..1023
                int e = idx >> 5;               // 0..31
                int j = (idx & 31) * 2;         // 0..62 even
                const float* rr = res + e * 8;
                float a0 = 0.f, a1 = 0.f;
                #pragma unroll
                for (int k = 0; k < 8; k++) {
                    float r = rr[k];
                    a0 = fmaf(r, wr1s[k * 64 + j], a0);
                    a1 = fmaf(r, wr1s[k * 64 + j + 1], a1);
                }
                float h0 = __fdividef(a0, 1.f + __expf(-a0));
                float h1 = __fdividef(a1, 1.f + __expf(-a1));
                *(half2*)(hu + e * 72 + j) = __floats2half2_rn(h0, h1);
            }
            asm volatile("bar.sync 1, 256;" ::: "memory");

            // MMA: C[32,320] = h @ W_r2 (fp16 in, fp32 accum), warp = 40-col strip
            float c[2][5][4];
            #pragma unroll
            for (int mt = 0; mt < 2; mt++)
                #pragma unroll
                for (int nt = 0; nt < 5; nt++)
                    #pragma unroll
                    for (int q = 0; q < 4; q++) c[mt][nt][q] = 0.f;

            #pragma unroll
            for (int ks = 0; ks < 4; ks++) {
                int kb = ks * 16;
                unsigned a[2][4];
                #pragma unroll
                for (int mt = 0; mt < 2; mt++) {
                    int r0 = mt * 16 + gid;
                    a[mt][0] = *(const unsigned*)(hu + r0 * 72 + kb + 2 * tig);
                    a[mt][1] = *(const unsigned*)(hu + (r0 + 8) * 72 + kb + 2 * tig);
                    a[mt][2] = *(const unsigned*)(hu + r0 * 72 + kb + 2 * tig + 8);
                    a[mt][3] = *(const unsigned*)(hu + (r0 + 8) * 72 + kb + 2 * tig + 8);
                }
                #pragma unroll
                for (int nt = 0; nt < 5; nt++) {
                    int col = warp * 40 + nt * 8 + gid;
                    unsigned b0 = *(const unsigned*)(wr2t + col * 72 + kb + 2 * tig);
                    unsigned b1 = *(const unsigned*)(wr2t + col * 72 + kb + 2 * tig + 8);
                    #pragma unroll
                    for (int mt = 0; mt < 2; mt++) {
                        asm volatile(
                            "mma.sync.aligned.m16n8k16.row.col.f32.f16.f16.f32 "
                            "{%0,%1,%2,%3}, {%4,%5,%6,%7}, {%8,%9}, {%0,%1,%2,%3};\n"
                            : "+f"(c[mt][nt][0]), "+f"(c[mt][nt][1]),
                              "+f"(c[mt][nt][2]), "+f"(c[mt][nt][3])
                            : "r"(a[mt][0]), "r"(a[mt][1]), "r"(a[mt][2]), "r"(a[mt][3]),
                              "r"(b0), "r"(b1));
                    }
                }
            }
            // store C fragments into bufP as fp16
            #pragma unroll
            for (int mt = 0; mt < 2; mt++) {
                int r0 = mt * 16 + gid;
                #pragma unroll
                for (int nt = 0; nt < 5; nt++) {
                    int col = warp * 40 + nt * 8 + 2 * tig;
                    *(half2*)(bufP + r0 * 328 + col) =
                        __floats2half2_rn(c[mt][nt][0], c[mt][nt][1]);
                    *(half2*)(bufP + (r0 + 8) * 328 + col) =
                        __floats2half2_rn(c[mt][nt][2], c[mt][nt][3]);
                }
            }
        }

        if (!producer && tC >= 0) {
            int e0 = tC << 5;
            int cw = warp - 8;
            #pragma unroll
            for (int i = 0; i < 4; i++) {
                int el = cw * 4 + i;
                int e = e0 + el;
                if (e < En) {
                    const __half* cwp = bufC + el * 328;
                    float2 w0 = __half22float2(*(const half2*)(cwp + 2 * lane));
                    float2 w1 = __half22float2(*(const half2*)(cwp + 64 + 2 * lane));
                    float2 w2 = __half22float2(*(const half2*)(cwp + 128 + 2 * lane));
                    float2 w3 = __half22float2(*(const half2*)(cwp + 192 + 2 * lane));
                    float2 w4 = __half22float2(*(const half2*)(cwp + 256 + 2 * lane));

                    int s = __ldg(senders + e);
                    int r = __ldg(receivers + e);
                    float vx = __ldg(vectors + (size_t)e * 3 + 0);
                    float vy = __ldg(vectors + (size_t)e * 3 + 1);
                    float vz = __ldg(vectors + (size_t)e * 3 + 2);
                    float nrm = sqrtf(vx * vx + vy * vy + vz * vz);
                    float ri = 1.f / (nrm + 1e-9f);
                    float Y0 = vx * ri, Y1 = vy * ri, Y2 = vz * ri;

                    float2 xs = __ldg((const float2*)(g_S + (size_t)s * 64) + lane);
                    const float2* Vp = (const float2*)(g_V + (size_t)s * 192);
                    float2 p0 = __ldg(Vp + lane * 3 + 0);
                    float2 p1 = __ldg(Vp + lane * 3 + 1);
                    float2 p2 = __ldg(Vp + lane * 3 + 2);
                    float a0 = p0.x, a1 = p0.y, a2 = p1.x;
                    float b0 = p1.y, b1 = p2.x, b2 = p2.y;

                    float dota = a0 * Y0 + a1 * Y1 + a2 * Y2;
                    float dotb = b0 * Y0 + b1 * Y1 + b2 * Y2;

                    float msa = w0.x * xs.x + w3.x * dota;
                    float msb = w0.y * xs.y + w3.y * dotb;

                    float cxa0 = a1 * Y2 - a2 * Y1;
                    float cxa1 = a2 * Y0 - a0 * Y2;
                    float cxa2 = a0 * Y1 - a1 * Y0;
                    float cxb0 = b1 * Y2 - b2 * Y1;
                    float cxb1 = b2 * Y0 - b0 * Y2;
                    float cxb2 = b0 * Y1 - b1 * Y0;

                    float sa = w1.x * xs.x, sb = w1.y * xs.y;
                    float mva0 = sa * Y0 + w2.x * a0 + w4.x * cxa0;
                    float mva1 = sa * Y1 + w2.x * a1 + w4.x * cxa1;
                    float mva2 = sa * Y2 + w2.x * a2 + w4.x * cxa2;
                    float mvb0 = sb * Y0 + w2.y * b0 + w4.y * cxb0;
                    float mvb1 = sb * Y1 + w2.y * b1 + w4.y * cxb1;
                    float mvb2 = sb * Y2 + w2.y * b2 + w4.y * cxb2;

                    float* base = g_A + (size_t)r * 256 + lane * 8;
                    asm volatile("red.global.add.v4.f32 [%0], {%1,%2,%3,%4};"
                                 :: "l"(base), "f"(msa), "f"(mva0), "f"(mva1), "f"(mva2)
                                 : "memory");
                    asm volatile("red.global.add.v4.f32 [%0], {%1,%2,%3,%4};"
                                 :: "l"(base + 4), "f"(msb), "f"(mvb0), "f"(mvb1), "f"(mvb2)
                                 : "memory");
                }
            }
        }
        __syncthreads();
        p ^= 1;
    }
}

// ============================================================================
// Kernel C: node post. Blocks own ONE species (skip weights staged in smem).
// ============================================================================
__global__ __launch_bounds__(256) void k_node(
    const float* __restrict__ nfs, const float* __restrict__ nfv,
    const float* __restrict__ Wds, const float* __restrict__ Wdv,
    const float* __restrict__ wsym_s, const float* __restrict__ wsym_v,
    const float* __restrict__ WLs, const float* __restrict__ WLv,
    const float* __restrict__ Wsk_s, const float* __restrict__ Wsk_v,
    const float* __restrict__ Wout,
    float* __restrict__ out0, float* __restrict__ fsO, float* __restrict__ fvO)
{
    extern __shared__ float sn[];
    float4* wd4  = (float4*)sn;
    float4* wl4  = (float4*)(sn + 8192);
    float4* sk4  = (float4*)(sn + 16384);
    float*  wsym = sn + 24576;
    float*  wout = sn + 24896;
    float4* aggb = (float4*)(sn + 24960);
    float4* nfb  = (float4*)(sn + 24960 + 8192);
    float4* psb  = (float4*)(sn + 24960 + 16384);

    int tid = threadIdx.x;
    int sp = blockIdx.y;

    {
        const float2* ds2 = (const float2*)Wds;
        const float2* dv2 = (const float2*)Wdv;
        const float2* ls2 = (const float2*)WLs;
        const float2* lv2 = (const float2*)WLv;
        const float2* ss2 = (const float2*)(Wsk_s + (size_t)sp * 4096);
        const float2* sv2 = (const float2*)(Wsk_v + (size_t)sp * 4096);
        for (int i = tid; i < 2048; i += 256) {
            float2 a = ds2[i], b = dv2[i];
            wd4[i] = make_float4(a.x, b.x, a.y, b.y);
            float2 cl = ls2[i], dl = lv2[i];
            wl4[i] = make_float4(cl.x, dl.x, cl.y, dl.y);
            float2 e = ss2[i], f = sv2[i];
            sk4[i] = make_float4(e.x, f.x, e.y, f.y);
        }
        for (int i = tid; i < 192; i += 256) wsym[i] = wsym_s[sp * 192 + i];
        for (int i = tid; i < 128; i += 256) wsym[192 + i] = wsym_v[sp * 128 + i];
        if (tid < 64) wout[tid] = Wout[tid];
    }
    __syncthreads();

    int warp = tid >> 5, lane = tid & 31;
    float4* ab = aggb + warp * 256;
    float4* nb = nfb + warp * 256;
    float4* pb = psb + warp * 256;
    int cnt = g_cnt[sp];
    const int* lst = g_bkt + sp * NN;
    const float* ws0 = wsym, *ws1 = wsym + 64, *ws2 = wsym + 128;
    const float* wv0 = wsym + 192, *wv1 = wsym + 256;

    for (int base = blockIdx.x * 32 + warp * 4; base < cnt; base += gridDim.x * 32) {
        int nv = cnt - base; if (nv > 4) nv = 4;
        int nn[4];
        #pragma unroll
        for (int j = 0; j < 4; j++) nn[j] = lst[base + ((j < nv) ? j : 0)];

        #pragma unroll
        for (int j = 0; j < 4; j++) {
            int n = nn[j];
            const float4* ga = (const float4*)g_A + (size_t)n * 64;
            ab[j * 64 + 2 * lane]     = ga[2 * lane];
            ab[j * 64 + 2 * lane + 1] = ga[2 * lane + 1];
            float2 sv = *(const float2*)(nfs + (size_t)n * 64 + 2 * lane);
            const float2* vp = (const float2*)(nfv + (size_t)n * 192);
            float2 p0 = vp[lane * 3], p1 = vp[lane * 3 + 1], p2 = vp[lane * 3 + 2];
            nb[j * 64 + 2 * lane]     = make_float4(sv.x, p0.x, p0.y, p1.x);
            nb[j * 64 + 2 * lane + 1] = make_float4(sv.y, p1.y, p2.x, p2.y);
        }
        __syncwarp();

        float acc[4][8];
        #pragma unroll
        for (int j = 0; j < 4; j++)
            #pragma unroll
            for (int q = 0; q < 8; q++) acc[j][q] = 0.f;

        #pragma unroll 4
        for (int f = 0; f < 64; f++) {
            float4 wq = wd4[f * 32 + lane];
            #pragma unroll
            for (int j = 0; j < 4; j++) {
                float4 a = ab[j * 64 + f];
                acc[j][0] = fmaf(a.x, wq.x, acc[j][0]);
                acc[j][1] = fmaf(a.y, wq.y, acc[j][1]);
                acc[j][2] = fmaf(a.z, wq.y, acc[j][2]);
                acc[j][3] = fmaf(a.w, wq.y, acc[j][3]);
                acc[j][4] = fmaf(a.x, wq.z, acc[j][4]);
                acc[j][5] = fmaf(a.y, wq.w, acc[j][5]);
                acc[j][6] = fmaf(a.z, wq.w, acc[j][6]);
                acc[j][7] = fmaf(a.w, wq.w, acc[j][7]);
            }
        }

        int c0 = 2 * lane, c1 = 2 * lane + 1;
        #pragma unroll
        for (int j = 0; j < 4; j++) {
            float sa0 = acc[j][0] * 0.25f, va0 = acc[j][1] * 0.25f;
            float va1 = acc[j][2] * 0.25f, va2 = acc[j][3] * 0.25f;
            float sa1 = acc[j][4] * 0.25f, vb0 = acc[j][5] * 0.25f;
            float vb1 = acc[j][6] * 0.25f, vb2 = acc[j][7] * 0.25f;
            float ps0 = ws0[c0] * sa0 + ws1[c0] * sa0 * sa0
                      + ws2[c0] * (va0 * va0 + va1 * va1 + va2 * va2);
            float cc0 = wv0[c0] + wv1[c0] * sa0;
            float ps1 = ws0[c1] * sa1 + ws1[c1] * sa1 * sa1
                      + ws2[c1] * (vb0 * vb0 + vb1 * vb1 + vb2 * vb2);
            float cc1 = wv0[c1] + wv1[c1] * sa1;
            pb[j * 64 + c0] = make_float4(ps0, cc0 * va0, cc0 * va1, cc0 * va2);
            pb[j * 64 + c1] = make_float4(ps1, cc1 * vb0, cc1 * vb1, cc1 * vb2);
        }
        __syncwarp();

        float a2c[4][8];
        #pragma unroll
        for (int j = 0; j < 4; j++)
            #pragma unroll
            for (int q = 0; q < 8; q++) a2c[j][q] = 0.f;

        #pragma unroll 4
        for (int f = 0; f < 64; f++) {
            float4 wl = wl4[f * 32 + lane];
            float4 sk = sk4[f * 32 + lane];
            #pragma unroll
            for (int j = 0; j < 4; j++) {
                float4 p = pb[j * 64 + f];
                float4 q = nb[j * 64 + f];
                a2c[j][0] = fmaf(p.x, wl.x, fmaf(q.x, sk.x, a2c[j][0]));
                a2c[j][1] = fmaf(p.y, wl.y, fmaf(q.y, sk.y, a2c[j][1]));
                a2c[j][2] = fmaf(p.z, wl.y, fmaf(q.z, sk.y, a2c[j][2]));
                a2c[j][3] = fmaf(p.w, wl.y, fmaf(q.w, sk.y, a2c[j][3]));
                a2c[j][4] = fmaf(p.x, wl.z, fmaf(q.x, sk.z, a2c[j][4]));
                a2c[j][5] = fmaf(p.y, wl.w, fmaf(q.y, sk.w, a2c[j][5]));
                a2c[j][6] = fmaf(p.z, wl.w, fmaf(q.z, sk.w, a2c[j][6]));
                a2c[j][7] = fmaf(p.w, wl.w, fmaf(q.w, sk.w, a2c[j][7]));
            }
        }

        #pragma unroll
        for (int j = 0; j < 4; j++) {
            int n = nn[j];
            float r = a2c[j][0] * wout[c0] + a2c[j][4] * wout[c1];
            #pragma unroll
            for (int off = 16; off > 0; off >>= 1)
                r += __shfl_xor_sync(0xffffffffu, r, off);
            if (j < nv) {
                *(float2*)(fsO + (size_t)n * 64 + c0) = make_float2(a2c[j][0], a2c[j][4]);
                float* vb = fvO + (size_t)n * 192 + 6 * lane;
                *(float2*)(vb)     = make_float2(a2c[j][1], a2c[j][2]);
                *(float2*)(vb + 2) = make_float2(a2c[j][3], a2c[j][5]);
                *(float2*)(vb + 4) = make_float2(a2c[j][6], a2c[j][7]);
                if (lane == 0) out0[n] = r;
            }
        }
        __syncwarp();
    }
}

// ============================================================================
extern "C" void kernel_launch(void* const* d_in, const int* in_sizes, int n_in,
                              void* d_out, int out_size)
{
    const float* vectors  = (const float*)d_in[0];
    const float* nfs      = (const float*)d_in[1];
    const float* nfv      = (const float*)d_in[2];
    const float* RE       = (const float*)d_in[3];
    const float* Wus      = (const float*)d_in[4];
    const float* Wuv      = (const float*)d_in[5];
    const float* Wr1      = (const float*)d_in[6];
    const float* Wr2      = (const float*)d_in[7];
    const float* Wds      = (const float*)d_in[8];
    const float* Wdv      = (const float*)d_in[9];
    const float* wsym_s   = (const float*)d_in[10];
    const float* wsym_v   = (const float*)d_in[11];
    const float* WLs      = (const float*)d_in[12];
    const float* WLv      = (const float*)d_in[13];
    const float* Wsk_s    = (const float*)d_in[14];
    const float* Wsk_v    = (const float*)d_in[15];
    const float* Wout     = (const float*)d_in[16];
    const int*   specie   = (const int*)d_in[17];
    const int*   senders  = (const int*)d_in[18];
    const int*   receivers= (const int*)d_in[19];

    int N = in_sizes[1] / 64;
    int E = in_sizes[18];
    if (N > NN) N = NN;
    if (E > EE) E = EE;

    float* out0 = (float*)d_out;
    float* fsO  = out0 + N;
    float* fvO  = fsO + (size_t)N * 64;

    const int UP_SMEM   = (8192 + 2048 + 8192) * 4;                 // 73728 B
    const int EDGE_SMEM = 23936 * 4;                                // 95744 B
    const int NODE_SMEM = (24960 + 3 * 8192) * 4;                   // 198144 B
    cudaFuncSetAttribute(k_up,   cudaFuncAttributeMaxDynamicSharedMemorySize, UP_SMEM);
    cudaFuncSetAttribute(k_edge, cudaFuncAttributeMaxDynamicSharedMemorySize, EDGE_SMEM);
    cudaFuncSetAttribute(k_node, cudaFuncAttributeMaxDynamicSharedMemorySize, NODE_SMEM);

    // species bucketing
    k_zero_cnt<<<1, 32>>>();
    k_bucket<<<(N + 255) / 256, 256>>>(specie, N);

    k_up<<<296, 256, UP_SMEM>>>(nfs, nfv, Wus, Wuv, N);
    k_edge<<<296, 512, EDGE_SMEM>>>(RE, Wr1, Wr2, vectors, senders, receivers, E);
    k_node<<<dim3(15, NSPEC), 256, NODE_SMEM>>>(nfs, nfv, Wds, Wdv,
                                                wsym_s, wsym_v, WLs, WLv,
                                                Wsk_s, Wsk_v, Wout,
                                                out0, fsO, fvO);
}